// round 5
// baseline (speedup 1.0000x reference)
#include <cuda_runtime.h>
#include <cuda_bf16.h>
#include <mma.h>

using namespace nvcuda;

#define T_TOK 4096
#define D_DIM 768
#define H_DIM 2688
#define E_NUM 8

#define BM 64
#define BN 64
#define BK 16

// ---------------- scratch (static device globals; no allocations) ----------------
__device__ float g_z_acc;
__device__ int   g_cnt[E_NUM];
__device__ int   g_tok[E_NUM * T_TOK];
__device__ float g_tw [E_NUM * T_TOK];
// activation scratch: [E*T, H] fp32 (tf32-rounded). 8*4096*2688*4 = 352 MB.
__device__ float g_act[(size_t)E_NUM * T_TOK * H_DIM];

// ---------------- kernel 0: zero output + counters ----------------
__global__ void k_zero(float* __restrict__ out, int out_size) {
    int i = blockIdx.x * blockDim.x + threadIdx.x;
    if (i < out_size) out[i] = 0.0f;
    if (blockIdx.x == 0) {
        if (threadIdx.x < E_NUM) g_cnt[threadIdx.x] = 0;
        if (threadIdx.x == 32)   g_z_acc = 0.0f;
    }
}

// ---------------- kernel 1: router ----------------
// one warp per token: 8 logits (dot over D=768), biased top-2, unbiased softmax,
// z-loss accumulation, atomic bucketing into per-expert token lists.
__global__ void k_router(const float* __restrict__ x,
                         const float* __restrict__ gw,
                         const float* __restrict__ bias) {
    int gwarp = (blockIdx.x * blockDim.x + threadIdx.x) >> 5;
    int lane  = threadIdx.x & 31;
    if (gwarp >= T_TOK) return;
    const float* xr = x + (size_t)gwarp * D_DIM;

    float xv[24];
#pragma unroll
    for (int i = 0; i < 24; i++) xv[i] = xr[i * 32 + lane];

    float lg[8];
#pragma unroll
    for (int e = 0; e < 8; e++) {
        const float* w = gw + e * D_DIM;
        float s = 0.0f;
#pragma unroll
        for (int i = 0; i < 24; i++) s += xv[i] * w[i * 32 + lane];
#pragma unroll
        for (int o = 16; o > 0; o >>= 1) s += __shfl_xor_sync(0xffffffffu, s, o);
        lg[e] = s;
    }

    if (lane == 0) {
        // top-2 on biased logits (strict > keeps lowest index on ties, like lax.top_k)
        float b1 = -1e30f, b2 = -1e30f; int i1 = 0, i2 = 0;
#pragma unroll
        for (int e = 0; e < 8; e++) {
            float b = lg[e] + bias[e];
            if (b > b1)      { b2 = b1; i2 = i1; b1 = b; i1 = e; }
            else if (b > b2) { b2 = b;  i2 = e; }
        }
        // softmax over UNbiased selected logits
        float l1 = lg[i1], l2 = lg[i2];
        float m = fmaxf(l1, l2);
        float e1 = expf(l1 - m), e2 = expf(l2 - m);
        float inv = 1.0f / (e1 + e2);
        float w1 = e1 * inv, w2 = e2 * inv;
        // z-loss: logsumexp over all 8 unbiased logits
        float mm = lg[0];
#pragma unroll
        for (int e = 1; e < 8; e++) mm = fmaxf(mm, lg[e]);
        float s = 0.0f;
#pragma unroll
        for (int e = 0; e < 8; e++) s += expf(lg[e] - mm);
        float lse = mm + logf(s);
        atomicAdd(&g_z_acc, lse * lse);

        int p1 = atomicAdd(&g_cnt[i1], 1);
        g_tok[i1 * T_TOK + p1] = gwarp;  g_tw[i1 * T_TOK + p1] = w1;
        int p2 = atomicAdd(&g_cnt[i2], 1);
        g_tok[i2 * T_TOK + p2] = gwarp;  g_tw[i2 * T_TOK + p2] = w2;
    }
}

// ---------------- kernel 2: grouped GEMM1 (gate+up fused, SiLU epilogue) ----------------
// per block: expert e, M-tile of 64 gathered tokens, N-tile of 64 hidden dims.
// computes g = X*Wg, u = X*Wu simultaneously (shared A), act = silu(g)*u -> g_act.
__global__ void __launch_bounds__(128) k_gemm1(const float* __restrict__ x,
                                               const float* __restrict__ wgate,
                                               const float* __restrict__ wup) {
    const int e   = blockIdx.z;
    const int cnt = g_cnt[e];
    const int m0  = blockIdx.x * BM;
    if (m0 >= cnt) return;
    const int n0  = blockIdx.y * BN;

    __shared__ union {
        struct { float A[BM][BK + 8]; float Bg[BK][BN + 8]; float Bu[BK][BN + 8]; } s;
        float C[BM][BN + 8];
    } sm;

    const int tid  = threadIdx.x;
    const int warp = tid >> 5;
    const int wm   = warp >> 1;    // 0..1
    const int wn   = warp & 1;     // 0..1

    wmma::fragment<wmma::accumulator, 16, 16, 8, float> accg[2][2], accu[2][2];
#pragma unroll
    for (int i = 0; i < 2; i++)
#pragma unroll
        for (int j = 0; j < 2; j++) {
            wmma::fill_fragment(accg[i][j], 0.0f);
            wmma::fill_fragment(accu[i][j], 0.0f);
        }

    // A-load mapping: 64 rows x 16 cols = 256 float4; 2 per thread, same row.
    const int a_row = tid >> 1;                 // 0..63
    const int a_c0  = (tid & 1) * 2;            // float4 col index base (0 or 2)
    const bool a_valid = (m0 + a_row) < cnt;
    const int a_tok = a_valid ? g_tok[e * T_TOK + m0 + a_row] : 0;
    // B-load mapping: 16 rows x 16 float4 per row; 2 per thread, same row.
    const int b_row = tid >> 3;                 // 0..15
    const int b_c0  = (tid & 7) * 2;            // 0..14

    const size_t wbase = (size_t)e * D_DIM * H_DIM;

    for (int kt = 0; kt < D_DIM / BK; kt++) {
        const int k0 = kt * BK;
#pragma unroll
        for (int q = 0; q < 2; q++) {
            float4 v = make_float4(0.f, 0.f, 0.f, 0.f);
            if (a_valid)
                v = *(const float4*)(x + (size_t)a_tok * D_DIM + k0 + (a_c0 + q) * 4);
            float* dst = &sm.s.A[a_row][(a_c0 + q) * 4];
            dst[0] = wmma::__float_to_tf32(v.x);
            dst[1] = wmma::__float_to_tf32(v.y);
            dst[2] = wmma::__float_to_tf32(v.z);
            dst[3] = wmma::__float_to_tf32(v.w);
        }
#pragma unroll
        for (int q = 0; q < 2; q++) {
            const size_t off = wbase + (size_t)(k0 + b_row) * H_DIM + n0 + (b_c0 + q) * 4;
            float4 vg = *(const float4*)(wgate + off);
            float4 vu = *(const float4*)(wup + off);
            float* dg = &sm.s.Bg[b_row][(b_c0 + q) * 4];
            float* du = &sm.s.Bu[b_row][(b_c0 + q) * 4];
            dg[0] = wmma::__float_to_tf32(vg.x); dg[1] = wmma::__float_to_tf32(vg.y);
            dg[2] = wmma::__float_to_tf32(vg.z); dg[3] = wmma::__float_to_tf32(vg.w);
            du[0] = wmma::__float_to_tf32(vu.x); du[1] = wmma::__float_to_tf32(vu.y);
            du[2] = wmma::__float_to_tf32(vu.z); du[3] = wmma::__float_to_tf32(vu.w);
        }
        __syncthreads();

#pragma unroll
        for (int kk = 0; kk < 2; kk++) {
            wmma::fragment<wmma::matrix_a, 16, 16, 8, wmma::precision::tf32, wmma::row_major> af[2];
            wmma::fragment<wmma::matrix_b, 16, 16, 8, wmma::precision::tf32, wmma::row_major> bgf[2], buf[2];
#pragma unroll
            for (int i = 0; i < 2; i++)
                wmma::load_matrix_sync(af[i], &sm.s.A[wm * 32 + i * 16][kk * 8], BK + 8);
#pragma unroll
            for (int j = 0; j < 2; j++) {
                wmma::load_matrix_sync(bgf[j], &sm.s.Bg[kk * 8][wn * 32 + j * 16], BN + 8);
                wmma::load_matrix_sync(buf[j], &sm.s.Bu[kk * 8][wn * 32 + j * 16], BN + 8);
            }
#pragma unroll
            for (int i = 0; i < 2; i++)
#pragma unroll
                for (int j = 0; j < 2; j++) {
                    wmma::mma_sync(accg[i][j], af[i], bgf[j], accg[i][j]);
                    wmma::mma_sync(accu[i][j], af[i], buf[j], accu[i][j]);
                }
        }
        __syncthreads();
    }

    // epilogue: act = silu(g) * u
#pragma unroll
    for (int i = 0; i < 2; i++)
#pragma unroll
        for (int j = 0; j < 2; j++) {
#pragma unroll
            for (int t = 0; t < accg[i][j].num_elements; t++) {
                float g = accg[i][j].x[t];
                float u = accu[i][j].x[t];
                float sg = 1.0f / (1.0f + expf(-g));
                accg[i][j].x[t] = g * sg * u;
            }
            wmma::store_matrix_sync(&sm.C[wm * 32 + i * 16][wn * 32 + j * 16],
                                    accg[i][j], BN + 8, wmma::mem_row_major);
        }
    __syncthreads();

    const int vrows = min(BM, cnt - m0);
    for (int idx = tid; idx < BM * BN; idx += 128) {
        int r = idx >> 6, c = idx & 63;
        if (r < vrows)
            g_act[((size_t)(e * T_TOK + m0 + r)) * H_DIM + n0 + c] =
                wmma::__float_to_tf32(sm.C[r][c]);
    }
}

// ---------------- kernel 3: grouped GEMM2 (down proj, weighted scatter-add) ----------------
__global__ void __launch_bounds__(128) k_gemm2(const float* __restrict__ wdown,
                                               float* __restrict__ out) {
    const int e   = blockIdx.z;
    const int cnt = g_cnt[e];
    const int m0  = blockIdx.x * BM;
    if (m0 >= cnt) return;
    const int n0  = blockIdx.y * BN;

    __shared__ union {
        struct { float A[BM][BK + 8]; float B[BK][BN + 8]; } s;
        float C[BM][BN + 8];
    } sm;

    const int tid  = threadIdx.x;
    const int warp = tid >> 5;
    const int wm   = warp >> 1;
    const int wn   = warp & 1;

    wmma::fragment<wmma::accumulator, 16, 16, 8, float> acc[2][2];
#pragma unroll
    for (int i = 0; i < 2; i++)
#pragma unroll
        for (int j = 0; j < 2; j++) wmma::fill_fragment(acc[i][j], 0.0f);

    const int a_row = tid >> 1;
    const int a_c0  = (tid & 1) * 2;
    const int b_row = tid >> 3;
    const int b_c0  = (tid & 7) * 2;
    const size_t abase = ((size_t)(e * T_TOK + m0)) * H_DIM;
    const size_t wbase = (size_t)e * H_DIM * D_DIM;

    for (int kt = 0; kt < H_DIM / BK; kt++) {
        const int k0 = kt * BK;
#pragma unroll
        for (int q = 0; q < 2; q++) {
            // padded rows carry stale (finite) data; their outputs are discarded.
            float4 v = *(const float4*)(g_act + abase + (size_t)a_row * H_DIM + k0 + (a_c0 + q) * 4);
            *(float4*)&sm.s.A[a_row][(a_c0 + q) * 4] = v;  // already tf32-rounded
        }
#pragma unroll
        for (int q = 0; q < 2; q++) {
            float4 v = *(const float4*)(wdown + wbase + (size_t)(k0 + b_row) * D_DIM + n0 + (b_c0 + q) * 4);
            float* d = &sm.s.B[b_row][(b_c0 + q) * 4];
            d[0] = wmma::__float_to_tf32(v.x); d[1] = wmma::__float_to_tf32(v.y);
            d[2] = wmma::__float_to_tf32(v.z); d[3] = wmma::__float_to_tf32(v.w);
        }
        __syncthreads();

#pragma unroll
        for (int kk = 0; kk < 2; kk++) {
            wmma::fragment<wmma::matrix_a, 16, 16, 8, wmma::precision::tf32, wmma::row_major> af[2];
            wmma::fragment<wmma::matrix_b, 16, 16, 8, wmma::precision::tf32, wmma::row_major> bf[2];
#pragma unroll
            for (int i = 0; i < 2; i++)
                wmma::load_matrix_sync(af[i], &sm.s.A[wm * 32 + i * 16][kk * 8], BK + 8);
#pragma unroll
            for (int j = 0; j < 2; j++)
                wmma::load_matrix_sync(bf[j], &sm.s.B[kk * 8][wn * 32 + j * 16], BN + 8);
#pragma unroll
            for (int i = 0; i < 2; i++)
#pragma unroll
                for (int j = 0; j < 2; j++)
                    wmma::mma_sync(acc[i][j], af[i], bf[j], acc[i][j]);
        }
        __syncthreads();
    }

#pragma unroll
    for (int i = 0; i < 2; i++)
#pragma unroll
        for (int j = 0; j < 2; j++)
            wmma::store_matrix_sync(&sm.C[wm * 32 + i * 16][wn * 32 + j * 16],
                                    acc[i][j], BN + 8, wmma::mem_row_major);
    __syncthreads();

    const int vrows = min(BM, cnt - m0);
    for (int idx = tid; idx < BM * BN; idx += 128) {
        int r = idx >> 6, c = idx & 63;
        if (r < vrows) {
            int tok = g_tok[e * T_TOK + m0 + r];
            float tw = g_tw[e * T_TOK + m0 + r];
            atomicAdd(&out[(size_t)tok * D_DIM + n0 + c], tw * sm.C[r][c]);
        }
    }
}

// ---------------- kernel 4: finalize z-loss ----------------
__global__ void k_final(float* __restrict__ out, int out_size) {
    if (out_size > T_TOK * D_DIM)
        out[T_TOK * D_DIM] = 1e-5f * g_z_acc / (float)T_TOK;
}

// ---------------- launcher ----------------
extern "C" void kernel_launch(void* const* d_in, const int* in_sizes, int n_in,
                              void* d_out, int out_size) {
    const float* x     = (const float*)d_in[0];  // [2,2048,768]
    const float* gw    = (const float*)d_in[1];  // [8,768]
    const float* bias  = (const float*)d_in[2];  // [8]
    const float* wgate = (const float*)d_in[3];  // [8,768,2688]
    const float* wup   = (const float*)d_in[4];  // [8,768,2688]
    const float* wdown = (const float*)d_in[5];  // [8,2688,768]
    float* out = (float*)d_out;

    k_zero<<<(out_size + 255) / 256, 256>>>(out, out_size);
    k_router<<<T_TOK / 8, 256>>>(x, gw, bias);

    dim3 g1(T_TOK / BM, H_DIM / BN, E_NUM);   // 64 x 42 x 8
    k_gemm1<<<g1, 128>>>(x, wgate, wup);

    dim3 g2(T_TOK / BM, D_DIM / BN, E_NUM);   // 64 x 12 x 8
    k_gemm2<<<g2, 128>>>(wdown, out);

    k_final<<<1, 1>>>(out, out_size);
}